// round 2
// baseline (speedup 1.0000x reference)
#include <cuda_runtime.h>
#include <math.h>

// Problem constants (fixed by the dataset)
#define Nn   10000
#define Ee   160000
#define E2e  320000

// ---------------- scratch (device globals; no allocs allowed) ----------------
__device__ float g_lg_ni[Ee * 256];
__device__ float g_lg_nj[Ee * 256];
__device__ float g_gfij [Ee * 256];
__device__ float g_lgfij[E2e * 256];
__device__ float g_gni  [Nn * 256];
__device__ float g_gnj  [Nn * 256];
__device__ float g_agg  [Ee * 128];
__device__ float g_cnt  [Ee];
__device__ float g_m1   [Ee * 256];
__device__ float g_m2   [Ee * 256];
__device__ float g_h1   [Ee * 256];
__device__ float g_h2   [Ee * 256];
__device__ float g_slg  [E2e * 4];
__device__ float g_maxlg[Ee * 4];
__device__ float g_denlg[Ee * 4];
__device__ float g_sg   [Ee * 4];
__device__ float g_maxg [Nn * 4];
__device__ float g_deng [Nn * 4];
__device__ float g_ag   [Ee * 4];
__device__ float g_acc1 [Ee * 256];
__device__ float g_acc2 [Ee * 256];

__device__ __forceinline__ float lrelu(float x) { return x > 0.f ? x : 0.01f * x; }

__device__ __forceinline__ void atomicMaxF(float* addr, float val) {
    int* ia = (int*)addr;
    int old = __float_as_int(*addr);
    while (__int_as_float(old) < val) {
        int assumed = old;
        old = atomicCAS(ia, assumed, __float_as_int(val));
        if (old == assumed) break;
    }
}

// ---------------- generic fp32 GEMM: C[M,Nc] = A[M,K] @ W[Nc,K]^T (+bias) ----
// 64x64 tile, 16-deep K slices, 4x4 per thread, float4 smem loads.
__global__ __launch_bounds__(256) void gemm_nt(const float* __restrict__ A,
                                               const float* __restrict__ W,
                                               const float* __restrict__ bias,
                                               float* __restrict__ C,
                                               int M, int Nc, int K)
{
    __shared__ float As[16][68];
    __shared__ float Ws[16][68];
    const int bm = blockIdx.y * 64;
    const int bn = blockIdx.x * 64;
    const int tid = threadIdx.x;
    const int lr = tid >> 2;          // 0..63 (load row)
    const int lk = (tid & 3) * 4;     // 0,4,8,12 (load k)
    const int tr = tid >> 4;          // 0..15
    const int tc = tid & 15;          // 0..15
    const int arow = bm + lr;
    float acc[4][4] = {};

    for (int k0 = 0; k0 < K; k0 += 16) {
        float4 a4 = make_float4(0.f, 0.f, 0.f, 0.f);
        if (arow < M)
            a4 = *(const float4*)(A + (size_t)arow * K + k0 + lk);
        float4 w4 = *(const float4*)(W + (size_t)(bn + lr) * K + k0 + lk);
        As[lk + 0][lr] = a4.x; As[lk + 1][lr] = a4.y;
        As[lk + 2][lr] = a4.z; As[lk + 3][lr] = a4.w;
        Ws[lk + 0][lr] = w4.x; Ws[lk + 1][lr] = w4.y;
        Ws[lk + 2][lr] = w4.z; Ws[lk + 3][lr] = w4.w;
        __syncthreads();
#pragma unroll
        for (int kk = 0; kk < 16; kk++) {
            float4 av = *(const float4*)&As[kk][tr * 4];
            float4 wv = *(const float4*)&Ws[kk][tc * 4];
            float a[4] = {av.x, av.y, av.z, av.w};
            float w[4] = {wv.x, wv.y, wv.z, wv.w};
#pragma unroll
            for (int i = 0; i < 4; i++)
#pragma unroll
                for (int j = 0; j < 4; j++)
                    acc[i][j] += a[i] * w[j];
        }
        __syncthreads();
    }
#pragma unroll
    for (int i = 0; i < 4; i++) {
        int row = bm + tr * 4 + i;
        if (row >= M) continue;
        int col = bn + tc * 4;
        float4 b4 = bias ? *(const float4*)(bias + col) : make_float4(0.f, 0.f, 0.f, 0.f);
        float4 o;
        o.x = acc[i][0] + b4.x; o.y = acc[i][1] + b4.y;
        o.z = acc[i][2] + b4.z; o.w = acc[i][3] + b4.w;
        *(float4*)(C + (size_t)row * Nc + col) = o;
    }
}

// ---------------- small kernels ----------------
__global__ void fill_kernel(float* p, float v, int n) {
    int t = blockIdx.x * blockDim.x + threadIdx.x;
    if (t < n) p[t] = v;
}

__global__ void count_kernel(const int* __restrict__ lgdst) {
    int e2 = blockIdx.x * blockDim.x + threadIdx.x;
    if (e2 < E2e) atomicAdd(&g_cnt[lgdst[e2]], 1.f);
}

__global__ void scatter_x_kernel(const int* __restrict__ lgdst, const float* __restrict__ x) {
    int t = blockIdx.x * blockDim.x + threadIdx.x;
    if (t >= E2e * 128) return;
    int e2 = t >> 7, c = t & 127;
    atomicAdd(&g_agg[(size_t)lgdst[e2] * 128 + c], x[t]);
}

__global__ void build_m1_kernel(const float* __restrict__ m_feats) {
    int t = blockIdx.x * blockDim.x + threadIdx.x;
    if (t >= Ee * 256) return;
    int e = t >> 8, c = t & 255;
    float v;
    if (c < 128) v = m_feats[(size_t)e * 128 + c];
    else         v = g_agg[(size_t)e * 128 + (c - 128)] / fmaxf(g_cnt[e], 1.f);
    g_m1[t] = v;
}

__global__ void build_m2_kernel(const float* __restrict__ l_feats,
                                const float* __restrict__ m_feats,
                                const int* __restrict__ gsrc,
                                const int* __restrict__ gdst) {
    int t = blockIdx.x * blockDim.x + threadIdx.x;
    if (t >= Ee * 256) return;
    int e = t >> 8, c = t & 255;
    float v;
    if (c < 128) v = l_feats[(size_t)gsrc[e] * 128 + c] + l_feats[(size_t)gdst[e] * 128 + c];
    else         v = m_feats[(size_t)e * 128 + (c - 128)];
    g_m2[t] = v;
}

// line-graph attention scores: one warp per l-graph edge
__global__ void lg_score_kernel(const int* __restrict__ src, const int* __restrict__ dst,
                                const float* __restrict__ attn, const float* __restrict__ bias) {
    int w = (blockIdx.x * blockDim.x + threadIdx.x) >> 5;
    if (w >= E2e) return;
    int lane = threadIdx.x & 31;
    int s = src[w], d = dst[w];
    const float* ni  = g_lg_ni + (size_t)s * 256;
    const float* nj  = g_lg_nj + (size_t)d * 256;
    const float* fij = g_lgfij + (size_t)w * 256;
    float p[4] = {0.f, 0.f, 0.f, 0.f};
#pragma unroll
    for (int j = 0; j < 8; j++) {
        int i = lane + 32 * j;
        float v = lrelu(ni[i] + nj[i] + fij[i] + bias[i]);
        p[j >> 1] += v * attn[i];
    }
#pragma unroll
    for (int h = 0; h < 4; h++)
#pragma unroll
        for (int o = 16; o > 0; o >>= 1)
            p[h] += __shfl_xor_sync(0xffffffffu, p[h], o);
    if (lane == 0) {
#pragma unroll
        for (int h = 0; h < 4; h++) {
            g_slg[(size_t)w * 4 + h] = p[h];
            atomicMaxF(&g_maxlg[(size_t)d * 4 + h], p[h]);
        }
    }
}

// base-graph attention scores: one warp per graph edge
__global__ void g_score_kernel(const int* __restrict__ src, const int* __restrict__ dst,
                               const float* __restrict__ attn, const float* __restrict__ bias) {
    int w = (blockIdx.x * blockDim.x + threadIdx.x) >> 5;
    if (w >= Ee) return;
    int lane = threadIdx.x & 31;
    int s = src[w], d = dst[w];
    const float* ni  = g_gni  + (size_t)s * 256;
    const float* nj  = g_gnj  + (size_t)d * 256;
    const float* fij = g_gfij + (size_t)w * 256;
    float p[4] = {0.f, 0.f, 0.f, 0.f};
#pragma unroll
    for (int j = 0; j < 8; j++) {
        int i = lane + 32 * j;
        float v = lrelu(ni[i] + nj[i] + fij[i] + bias[i]);
        p[j >> 1] += v * attn[i];
    }
#pragma unroll
    for (int h = 0; h < 4; h++)
#pragma unroll
        for (int o = 16; o > 0; o >>= 1)
            p[h] += __shfl_xor_sync(0xffffffffu, p[h], o);
    if (lane == 0) {
#pragma unroll
        for (int h = 0; h < 4; h++) {
            g_sg[(size_t)w * 4 + h] = p[h];
            atomicMaxF(&g_maxg[(size_t)d * 4 + h], p[h]);
        }
    }
}

__global__ void lg_exp_kernel(const int* __restrict__ dst) {
    int t = blockIdx.x * blockDim.x + threadIdx.x;
    if (t >= E2e * 4) return;
    int e2 = t >> 2, h = t & 3;
    int d = dst[e2];
    float v = expf(g_slg[t] - g_maxlg[(size_t)d * 4 + h]);
    g_slg[t] = v;
    atomicAdd(&g_denlg[(size_t)d * 4 + h], v);
}

__global__ void g_exp_kernel(const int* __restrict__ dst) {
    int t = blockIdx.x * blockDim.x + threadIdx.x;
    if (t >= Ee * 4) return;
    int e = t >> 2, h = t & 3;
    int d = dst[e];
    float v = expf(g_sg[t] - g_maxg[(size_t)d * 4 + h]);
    g_sg[t] = v;
    atomicAdd(&g_deng[(size_t)d * 4 + h], v);
}

__global__ void ag_kernel(const int* __restrict__ gdst) {
    int t = blockIdx.x * blockDim.x + threadIdx.x;
    if (t >= Ee * 4) return;
    int e = t >> 2, h = t & 3;
    g_ag[t] = g_sg[t] / g_deng[(size_t)gdst[e] * 4 + h];
}

__global__ void msg_kernel(const int* __restrict__ src, const int* __restrict__ dst) {
    int t = blockIdx.x * blockDim.x + threadIdx.x;
    if (t >= E2e * 256) return;
    int e2 = t >> 8, c = t & 255, h = c >> 6;
    int s = src[e2], d = dst[e2];
    float alg = g_slg[(size_t)e2 * 4 + h] / g_denlg[(size_t)d * 4 + h];
    atomicAdd(&g_acc1[(size_t)d * 256 + c], g_h1[(size_t)s * 256 + c] * alg);
    atomicAdd(&g_acc2[(size_t)d * 256 + c], g_h2[(size_t)s * 256 + c] * g_ag[(size_t)d * 4 + h]);
}

__global__ void final_kernel(float* __restrict__ out) {
    int t = blockIdx.x * blockDim.x + threadIdx.x;
    if (t >= Ee * 64) return;
    int e = t >> 6, c = t & 63;
    float o = 0.f;
#pragma unroll
    for (int h = 0; h < 4; h++) {
        o += lrelu(g_acc1[(size_t)e * 256 + h * 64 + c]);
        o += lrelu(g_acc2[(size_t)e * 256 + h * 64 + c]);
    }
    out[t] = o;
}

// ---------------- host launch ----------------
extern "C" void kernel_launch(void* const* d_in, const int* in_sizes, int n_in,
                              void* d_out, int out_size)
{
    const float *l_feats = (const float*)d_in[0];
    const float *m_feats = (const float*)d_in[1];
    const float *x_feats = (const float*)d_in[2];
    const float *W_lg_node, *b_lg_node, *W_lg_ni, *W_lg_fij, *W_lg_nj, *lg_attn, *bias_lg;
    const float *W_g_node, *b_g_node, *W_g_ni, *W_g_fij, *W_g_nj, *g_attn, *bias_g;
    const int *gsrc, *gdst, *lgsrc, *lgdst;

    if (in_sizes[3] == Ee) {  // setup_inputs dict order
        gsrc = (const int*)d_in[3];  gdst = (const int*)d_in[4];
        lgsrc = (const int*)d_in[5]; lgdst = (const int*)d_in[6];
        W_lg_node = (const float*)d_in[7];  b_lg_node = (const float*)d_in[8];
        W_lg_ni   = (const float*)d_in[9];  W_lg_fij  = (const float*)d_in[10];
        W_lg_nj   = (const float*)d_in[11]; lg_attn   = (const float*)d_in[12];
        bias_lg   = (const float*)d_in[13];
        W_g_node  = (const float*)d_in[14]; b_g_node  = (const float*)d_in[15];
        W_g_ni    = (const float*)d_in[16]; W_g_fij   = (const float*)d_in[17];
        W_g_nj    = (const float*)d_in[18]; g_attn    = (const float*)d_in[19];
        bias_g    = (const float*)d_in[20];
    } else {                  // reference() signature order
        W_lg_node = (const float*)d_in[3];  b_lg_node = (const float*)d_in[4];
        W_lg_ni   = (const float*)d_in[5];  W_lg_fij  = (const float*)d_in[6];
        W_lg_nj   = (const float*)d_in[7];  lg_attn   = (const float*)d_in[8];
        bias_lg   = (const float*)d_in[9];
        W_g_node  = (const float*)d_in[10]; b_g_node  = (const float*)d_in[11];
        W_g_ni    = (const float*)d_in[12]; W_g_fij   = (const float*)d_in[13];
        W_g_nj    = (const float*)d_in[14]; g_attn    = (const float*)d_in[15];
        bias_g    = (const float*)d_in[16];
        gsrc  = (const int*)d_in[17]; gdst  = (const int*)d_in[18];
        lgsrc = (const int*)d_in[19]; lgdst = (const int*)d_in[20];
    }

    float *p_lg_ni, *p_lg_nj, *p_gfij, *p_lgfij, *p_gni, *p_gnj;
    float *p_agg, *p_cnt, *p_m1, *p_m2, *p_h1, *p_h2;
    float *p_maxlg, *p_denlg, *p_maxg, *p_deng, *p_acc1, *p_acc2;
    cudaGetSymbolAddress((void**)&p_lg_ni, g_lg_ni);
    cudaGetSymbolAddress((void**)&p_lg_nj, g_lg_nj);
    cudaGetSymbolAddress((void**)&p_gfij,  g_gfij);
    cudaGetSymbolAddress((void**)&p_lgfij, g_lgfij);
    cudaGetSymbolAddress((void**)&p_gni,   g_gni);
    cudaGetSymbolAddress((void**)&p_gnj,   g_gnj);
    cudaGetSymbolAddress((void**)&p_agg,   g_agg);
    cudaGetSymbolAddress((void**)&p_cnt,   g_cnt);
    cudaGetSymbolAddress((void**)&p_m1,    g_m1);
    cudaGetSymbolAddress((void**)&p_m2,    g_m2);
    cudaGetSymbolAddress((void**)&p_h1,    g_h1);
    cudaGetSymbolAddress((void**)&p_h2,    g_h2);
    cudaGetSymbolAddress((void**)&p_maxlg, g_maxlg);
    cudaGetSymbolAddress((void**)&p_denlg, g_denlg);
    cudaGetSymbolAddress((void**)&p_maxg,  g_maxg);
    cudaGetSymbolAddress((void**)&p_deng,  g_deng);
    cudaGetSymbolAddress((void**)&p_acc1,  g_acc1);
    cudaGetSymbolAddress((void**)&p_acc2,  g_acc2);

    // ---- zero / init scratch ----
    cudaMemsetAsync(p_agg,   0, sizeof(float) * Ee * 128, 0);
    cudaMemsetAsync(p_cnt,   0, sizeof(float) * Ee, 0);
    cudaMemsetAsync(p_denlg, 0, sizeof(float) * Ee * 4, 0);
    cudaMemsetAsync(p_deng,  0, sizeof(float) * Nn * 4, 0);
    cudaMemsetAsync(p_acc1,  0, sizeof(float) * Ee * 256, 0);
    cudaMemsetAsync(p_acc2,  0, sizeof(float) * Ee * 256, 0);
    fill_kernel<<<(Ee * 4 + 255) / 256, 256>>>(p_maxlg, -INFINITY, Ee * 4);
    fill_kernel<<<(Nn * 4 + 255) / 256, 256>>>(p_maxg,  -INFINITY, Nn * 4);

    // ---- projection GEMMs ----
    dim3 blk(256);
    dim3 grdE (4, (Ee  + 63) / 64);
    dim3 grdE2(4, (E2e + 63) / 64);
    dim3 grdN (4, (Nn  + 63) / 64);
    gemm_nt<<<grdE,  blk>>>(m_feats, W_lg_ni,  nullptr, p_lg_ni, Ee,  256, 128);
    gemm_nt<<<grdE,  blk>>>(m_feats, W_lg_nj,  nullptr, p_lg_nj, Ee,  256, 128);
    gemm_nt<<<grdE,  blk>>>(m_feats, W_g_fij,  nullptr, p_gfij,  Ee,  256, 128);
    gemm_nt<<<grdE2, blk>>>(x_feats, W_lg_fij, nullptr, p_lgfij, E2e, 256, 128);
    gemm_nt<<<grdN,  blk>>>(l_feats, W_g_ni,   nullptr, p_gni,   Nn,  256, 128);
    gemm_nt<<<grdN,  blk>>>(l_feats, W_g_nj,   nullptr, p_gnj,   Nn,  256, 128);

    // ---- segment mean of x_feats onto l-graph nodes; node-update inputs ----
    count_kernel<<<(E2e + 255) / 256, 256>>>(lgdst);
    scatter_x_kernel<<<(E2e * 128 + 255) / 256, 256>>>(lgdst, x_feats);
    build_m1_kernel<<<(Ee * 256 + 255) / 256, 256>>>(m_feats);
    build_m2_kernel<<<(Ee * 256 + 255) / 256, 256>>>(l_feats, m_feats, gsrc, gdst);
    gemm_nt<<<grdE, blk>>>(p_m1, W_lg_node, b_lg_node, p_h1, Ee, 256, 256);
    gemm_nt<<<grdE, blk>>>(p_m2, W_g_node,  b_g_node,  p_h2, Ee, 256, 256);

    // ---- attention scores + edge softmax ----
    lg_score_kernel<<<(E2e * 32 + 255) / 256, 256>>>(lgsrc, lgdst, lg_attn, bias_lg);
    g_score_kernel <<<(Ee  * 32 + 255) / 256, 256>>>(gsrc,  gdst,  g_attn,  bias_g);
    lg_exp_kernel<<<(E2e * 4 + 255) / 256, 256>>>(lgdst);
    g_exp_kernel <<<(Ee  * 4 + 255) / 256, 256>>>(gdst);
    ag_kernel    <<<(Ee  * 4 + 255) / 256, 256>>>(gdst);

    // ---- weighted message aggregation + epilogue ----
    msg_kernel<<<(E2e * 256 + 255) / 256, 256>>>(lgsrc, lgdst);
    final_kernel<<<(Ee * 64 + 255) / 256, 256>>>((float*)d_out);
}

// round 4
// speedup vs baseline: 1.2665x; 1.2665x over previous
#include <cuda_runtime.h>
#include <math.h>

// Problem constants (fixed by the dataset)
#define Nn   10000
#define Ee   160000
#define E2e  320000

// ---------------- scratch (device globals; no allocs allowed) ----------------
__device__ float g_lg_ni[Ee * 256];
__device__ float g_lg_nj[Ee * 256];
__device__ float g_gfij [Ee * 256];
__device__ float g_lgfij[E2e * 256];
__device__ float g_gni  [Nn * 256];
__device__ float g_gnj  [Nn * 256];
__device__ float g_agg  [Ee * 128];
__device__ float g_cnt  [Ee];
__device__ float g_m1   [Ee * 256];
__device__ float g_m2   [Ee * 256];
__device__ float g_h1   [Ee * 256];
__device__ float g_h2   [Ee * 256];
__device__ float g_slg  [E2e * 4];
__device__ float g_maxlg[Ee * 4];
__device__ float g_denlg[Ee * 4];
__device__ float g_sg   [Ee * 4];
__device__ float g_maxg [Nn * 4];
__device__ float g_deng [Nn * 4];
__device__ float g_ag   [Ee * 4];
__device__ float g_acc1 [Ee * 256];
__device__ float g_acc2 [Ee * 256];

__device__ __forceinline__ float lrelu(float x) { return x > 0.f ? x : 0.01f * x; }

__device__ __forceinline__ void atomicMaxF(float* addr, float val) {
    int* ia = (int*)addr;
    int old = __float_as_int(*addr);
    while (__int_as_float(old) < val) {
        int assumed = old;
        old = atomicCAS(ia, assumed, __float_as_int(val));
        if (old == assumed) break;
    }
}

// ---------------- fp32 GEMM: C[M,Nc] = A[M,K] @ W[Nc,K]^T (+bias) -----------
// 128x128 tile, BK=16, 8x8 per thread (2x2 blocks of 4x4), double-buffered smem.
#define SMS 132   // smem row stride (floats), padded

__global__ __launch_bounds__(256) void gemm128(const float* __restrict__ A,
                                               const float* __restrict__ W,
                                               const float* __restrict__ bias,
                                               float* __restrict__ C,
                                               int M, int Nc, int K)
{
    __shared__ float As[2][16][SMS];
    __shared__ float Ws[2][16][SMS];
    const int bm = blockIdx.y * 128;
    const int bn = blockIdx.x * 128;
    const int tid = threadIdx.x;
    const int tr = tid >> 4;        // 0..15
    const int tc = tid & 15;        // 0..15
    // load assignment: 512 float4 per tile per matrix -> 2 per thread
    const int r0 = tid >> 1;              // 0..127
    const int c0 = (tid & 1) * 8;         // 0 or 8  (two float4: c0, c0+4)
    const int arow0 = bm + r0;
    const int wrow0 = bn + r0;

    float acc[8][8] = {};
    float4 pa0, pa1, pw0, pw1;

    const float4 z4 = make_float4(0.f, 0.f, 0.f, 0.f);

    // ---- prologue: fetch tile 0 ----
    {
        pa0 = (arow0 < M) ? *(const float4*)(A + (size_t)arow0 * K + 0 + c0)     : z4;
        pa1 = (arow0 < M) ? *(const float4*)(A + (size_t)arow0 * K + 0 + c0 + 4) : z4;
        pw0 = *(const float4*)(W + (size_t)wrow0 * K + 0 + c0);
        pw1 = *(const float4*)(W + (size_t)wrow0 * K + 0 + c0 + 4);
        As[0][c0 + 0][r0] = pa0.x; As[0][c0 + 1][r0] = pa0.y;
        As[0][c0 + 2][r0] = pa0.z; As[0][c0 + 3][r0] = pa0.w;
        As[0][c0 + 4][r0] = pa1.x; As[0][c0 + 5][r0] = pa1.y;
        As[0][c0 + 6][r0] = pa1.z; As[0][c0 + 7][r0] = pa1.w;
        Ws[0][c0 + 0][r0] = pw0.x; Ws[0][c0 + 1][r0] = pw0.y;
        Ws[0][c0 + 2][r0] = pw0.z; Ws[0][c0 + 3][r0] = pw0.w;
        Ws[0][c0 + 4][r0] = pw1.x; Ws[0][c0 + 5][r0] = pw1.y;
        Ws[0][c0 + 6][r0] = pw1.z; Ws[0][c0 + 7][r0] = pw1.w;
    }
    __syncthreads();

    const int nk = K >> 4;
    for (int t = 0; t < nk; t++) {
        const int cur = t & 1;
        if (t + 1 < nk) {
            const int k0 = (t + 1) << 4;
            pa0 = (arow0 < M) ? *(const float4*)(A + (size_t)arow0 * K + k0 + c0)     : z4;
            pa1 = (arow0 < M) ? *(const float4*)(A + (size_t)arow0 * K + k0 + c0 + 4) : z4;
            pw0 = *(const float4*)(W + (size_t)wrow0 * K + k0 + c0);
            pw1 = *(const float4*)(W + (size_t)wrow0 * K + k0 + c0 + 4);
        }
#pragma unroll
        for (int kk = 0; kk < 16; kk++) {
            float4 aA = *(const float4*)&As[cur][kk][tr * 4];
            float4 aB = *(const float4*)&As[cur][kk][tr * 4 + 64];
            float4 wA = *(const float4*)&Ws[cur][kk][tc * 4];
            float4 wB = *(const float4*)&Ws[cur][kk][tc * 4 + 64];
            float a[8] = {aA.x, aA.y, aA.z, aA.w, aB.x, aB.y, aB.z, aB.w};
            float w[8] = {wA.x, wA.y, wA.z, wA.w, wB.x, wB.y, wB.z, wB.w};
#pragma unroll
            for (int i = 0; i < 8; i++)
#pragma unroll
                for (int j = 0; j < 8; j++)
                    acc[i][j] += a[i] * w[j];
        }
        if (t + 1 < nk) {
            const int nxt = cur ^ 1;
            As[nxt][c0 + 0][r0] = pa0.x; As[nxt][c0 + 1][r0] = pa0.y;
            As[nxt][c0 + 2][r0] = pa0.z; As[nxt][c0 + 3][r0] = pa0.w;
            As[nxt][c0 + 4][r0] = pa1.x; As[nxt][c0 + 5][r0] = pa1.y;
            As[nxt][c0 + 6][r0] = pa1.z; As[nxt][c0 + 7][r0] = pa1.w;
            Ws[nxt][c0 + 0][r0] = pw0.x; Ws[nxt][c0 + 1][r0] = pw0.y;
            Ws[nxt][c0 + 2][r0] = pw0.z; Ws[nxt][c0 + 3][r0] = pw0.w;
            Ws[nxt][c0 + 4][r0] = pw1.x; Ws[nxt][c0 + 5][r0] = pw1.y;
            Ws[nxt][c0 + 6][r0] = pw1.z; Ws[nxt][c0 + 7][r0] = pw1.w;
            __syncthreads();
        }
    }

    // ---- epilogue ----
#pragma unroll
    for (int ih = 0; ih < 2; ih++) {
#pragma unroll
        for (int i = 0; i < 4; i++) {
            int row = bm + ih * 64 + tr * 4 + i;
            if (row >= M) continue;
#pragma unroll
            for (int jh = 0; jh < 2; jh++) {
                int col = bn + jh * 64 + tc * 4;
                float4 b4 = bias ? *(const float4*)(bias + col) : make_float4(0.f, 0.f, 0.f, 0.f);
                float4 o;
                o.x = acc[ih * 4 + i][jh * 4 + 0] + b4.x;
                o.y = acc[ih * 4 + i][jh * 4 + 1] + b4.y;
                o.z = acc[ih * 4 + i][jh * 4 + 2] + b4.z;
                o.w = acc[ih * 4 + i][jh * 4 + 3] + b4.w;
                *(float4*)(C + (size_t)row * Nc + col) = o;
            }
        }
    }
}

// ---------------- small kernels ----------------
__global__ void fill_kernel(float* p, float v, int n) {
    int t = blockIdx.x * blockDim.x + threadIdx.x;
    if (t < n) p[t] = v;
}

__global__ void count_kernel(const int* __restrict__ lgdst) {
    int e2 = blockIdx.x * blockDim.x + threadIdx.x;
    if (e2 < E2e) atomicAdd(&g_cnt[lgdst[e2]], 1.f);
}

__global__ void scatter_x_kernel(const int* __restrict__ lgdst, const float* __restrict__ x) {
    int t = blockIdx.x * blockDim.x + threadIdx.x;
    if (t >= E2e * 128) return;
    int e2 = t >> 7, c = t & 127;
    atomicAdd(&g_agg[(size_t)lgdst[e2] * 128 + c], x[t]);
}

__global__ void build_m1_kernel(const float* __restrict__ m_feats) {
    int t = blockIdx.x * blockDim.x + threadIdx.x;
    if (t >= Ee * 256) return;
    int e = t >> 8, c = t & 255;
    float v;
    if (c < 128) v = m_feats[(size_t)e * 128 + c];
    else         v = g_agg[(size_t)e * 128 + (c - 128)] / fmaxf(g_cnt[e], 1.f);
    g_m1[t] = v;
}

__global__ void build_m2_kernel(const float* __restrict__ l_feats,
                                const float* __restrict__ m_feats,
                                const int* __restrict__ gsrc,
                                const int* __restrict__ gdst) {
    int t = blockIdx.x * blockDim.x + threadIdx.x;
    if (t >= Ee * 256) return;
    int e = t >> 8, c = t & 255;
    float v;
    if (c < 128) v = l_feats[(size_t)gsrc[e] * 128 + c] + l_feats[(size_t)gdst[e] * 128 + c];
    else         v = m_feats[(size_t)e * 128 + (c - 128)];
    g_m2[t] = v;
}

// line-graph attention scores: one warp per l-graph edge
__global__ void lg_score_kernel(const int* __restrict__ src, const int* __restrict__ dst,
                                const float* __restrict__ attn, const float* __restrict__ bias) {
    int w = (blockIdx.x * blockDim.x + threadIdx.x) >> 5;
    if (w >= E2e) return;
    int lane = threadIdx.x & 31;
    int s = src[w], d = dst[w];
    const float* ni  = g_lg_ni + (size_t)s * 256;
    const float* nj  = g_lg_nj + (size_t)d * 256;
    const float* fij = g_lgfij + (size_t)w * 256;
    float p[4] = {0.f, 0.f, 0.f, 0.f};
#pragma unroll
    for (int j = 0; j < 8; j++) {
        int i = lane + 32 * j;
        float v = lrelu(ni[i] + nj[i] + fij[i] + bias[i]);
        p[j >> 1] += v * attn[i];
    }
#pragma unroll
    for (int h = 0; h < 4; h++)
#pragma unroll
        for (int o = 16; o > 0; o >>= 1)
            p[h] += __shfl_xor_sync(0xffffffffu, p[h], o);
    if (lane == 0) {
#pragma unroll
        for (int h = 0; h < 4; h++) {
            g_slg[(size_t)w * 4 + h] = p[h];
            atomicMaxF(&g_maxlg[(size_t)d * 4 + h], p[h]);
        }
    }
}

// base-graph attention scores: one warp per graph edge
__global__ void g_score_kernel(const int* __restrict__ src, const int* __restrict__ dst,
                               const float* __restrict__ attn, const float* __restrict__ bias) {
    int w = (blockIdx.x * blockDim.x + threadIdx.x) >> 5;
    if (w >= Ee) return;
    int lane = threadIdx.x & 31;
    int s = src[w], d = dst[w];
    const float* ni  = g_gni  + (size_t)s * 256;
    const float* nj  = g_gnj  + (size_t)d * 256;
    const float* fij = g_gfij + (size_t)w * 256;
    float p[4] = {0.f, 0.f, 0.f, 0.f};
#pragma unroll
    for (int j = 0; j < 8; j++) {
        int i = lane + 32 * j;
        float v = lrelu(ni[i] + nj[i] + fij[i] + bias[i]);
        p[j >> 1] += v * attn[i];
    }
#pragma unroll
    for (int h = 0; h < 4; h++)
#pragma unroll
        for (int o = 16; o > 0; o >>= 1)
            p[h] += __shfl_xor_sync(0xffffffffu, p[h], o);
    if (lane == 0) {
#pragma unroll
        for (int h = 0; h < 4; h++) {
            g_sg[(size_t)w * 4 + h] = p[h];
            atomicMaxF(&g_maxg[(size_t)d * 4 + h], p[h]);
        }
    }
}

__global__ void lg_exp_kernel(const int* __restrict__ dst) {
    int t = blockIdx.x * blockDim.x + threadIdx.x;
    if (t >= E2e * 4) return;
    int e2 = t >> 2, h = t & 3;
    int d = dst[e2];
    float v = expf(g_slg[t] - g_maxlg[(size_t)d * 4 + h]);
    g_slg[t] = v;
    atomicAdd(&g_denlg[(size_t)d * 4 + h], v);
}

__global__ void g_exp_kernel(const int* __restrict__ dst) {
    int t = blockIdx.x * blockDim.x + threadIdx.x;
    if (t >= Ee * 4) return;
    int e = t >> 2, h = t & 3;
    int d = dst[e];
    float v = expf(g_sg[t] - g_maxg[(size_t)d * 4 + h]);
    g_sg[t] = v;
    atomicAdd(&g_deng[(size_t)d * 4 + h], v);
}

__global__ void ag_kernel(const int* __restrict__ gdst) {
    int t = blockIdx.x * blockDim.x + threadIdx.x;
    if (t >= Ee * 4) return;
    int e = t >> 2, h = t & 3;
    g_ag[t] = g_sg[t] / g_deng[(size_t)gdst[e] * 4 + h];
}

__global__ void msg_kernel(const int* __restrict__ src, const int* __restrict__ dst) {
    int t = blockIdx.x * blockDim.x + threadIdx.x;
    if (t >= E2e * 256) return;
    int e2 = t >> 8, c = t & 255, h = c >> 6;
    int s = src[e2], d = dst[e2];
    float alg = g_slg[(size_t)e2 * 4 + h] / g_denlg[(size_t)d * 4 + h];
    atomicAdd(&g_acc1[(size_t)d * 256 + c], g_h1[(size_t)s * 256 + c] * alg);
    atomicAdd(&g_acc2[(size_t)d * 256 + c], g_h2[(size_t)s * 256 + c] * g_ag[(size_t)d * 4 + h]);
}

__global__ void final_kernel(float* __restrict__ out) {
    int t = blockIdx.x * blockDim.x + threadIdx.x;
    if (t >= Ee * 64) return;
    int e = t >> 6, c = t & 63;
    float o = 0.f;
#pragma unroll
    for (int h = 0; h < 4; h++) {
        o += lrelu(g_acc1[(size_t)e * 256 + h * 64 + c]);
        o += lrelu(g_acc2[(size_t)e * 256 + h * 64 + c]);
    }
    out[t] = o;
}

// ---------------- host launch ----------------
extern "C" void kernel_launch(void* const* d_in, const int* in_sizes, int n_in,
                              void* d_out, int out_size)
{
    const float *l_feats = (const float*)d_in[0];
    const float *m_feats = (const float*)d_in[1];
    const float *x_feats = (const float*)d_in[2];
    const float *W_lg_node, *b_lg_node, *W_lg_ni, *W_lg_fij, *W_lg_nj, *lg_attn, *bias_lg;
    const float *W_g_node, *b_g_node, *W_g_ni, *W_g_fij, *W_g_nj, *g_attn, *bias_g;
    const int *gsrc, *gdst, *lgsrc, *lgdst;

    if (in_sizes[3] == Ee) {  // setup_inputs dict order
        gsrc = (const int*)d_in[3];  gdst = (const int*)d_in[4];
        lgsrc = (const int*)d_in[5]; lgdst = (const int*)d_in[6];
        W_lg_node = (const float*)d_in[7];  b_lg_node = (const float*)d_in[8];
        W_lg_ni   = (const float*)d_in[9];  W_lg_fij  = (const float*)d_in[10];
        W_lg_nj   = (const float*)d_in[11]; lg_attn   = (const float*)d_in[12];
        bias_lg   = (const float*)d_in[13];
        W_g_node  = (const float*)d_in[14]; b_g_node  = (const float*)d_in[15];
        W_g_ni    = (const float*)d_in[16]; W_g_fij   = (const float*)d_in[17];
        W_g_nj    = (const float*)d_in[18]; g_attn    = (const float*)d_in[19];
        bias_g    = (const float*)d_in[20];
    } else {                  // reference() signature order
        W_lg_node = (const float*)d_in[3];  b_lg_node = (const float*)d_in[4];
        W_lg_ni   = (const float*)d_in[5];  W_lg_fij  = (const float*)d_in[6];
        W_lg_nj   = (const float*)d_in[7];  lg_attn   = (const float*)d_in[8];
        bias_lg   = (const float*)d_in[9];
        W_g_node  = (const float*)d_in[10]; b_g_node  = (const float*)d_in[11];
        W_g_ni    = (const float*)d_in[12]; W_g_fij   = (const float*)d_in[13];
        W_g_nj    = (const float*)d_in[14]; g_attn    = (const float*)d_in[15];
        bias_g    = (const float*)d_in[16];
        gsrc  = (const int*)d_in[17]; gdst  = (const int*)d_in[18];
        lgsrc = (const int*)d_in[19]; lgdst = (const int*)d_in[20];
    }

    float *p_lg_ni, *p_lg_nj, *p_gfij, *p_lgfij, *p_gni, *p_gnj;
    float *p_agg, *p_cnt, *p_m1, *p_m2, *p_h1, *p_h2;
    float *p_maxlg, *p_denlg, *p_maxg, *p_deng, *p_acc1, *p_acc2;
    cudaGetSymbolAddress((void**)&p_lg_ni, g_lg_ni);
    cudaGetSymbolAddress((void**)&p_lg_nj, g_lg_nj);
    cudaGetSymbolAddress((void**)&p_gfij,  g_gfij);
    cudaGetSymbolAddress((void**)&p_lgfij, g_lgfij);
    cudaGetSymbolAddress((void**)&p_gni,   g_gni);
    cudaGetSymbolAddress((void**)&p_gnj,   g_gnj);
    cudaGetSymbolAddress((void**)&p_agg,   g_agg);
    cudaGetSymbolAddress((void**)&p_cnt,   g_cnt);
    cudaGetSymbolAddress((void**)&p_m1,    g_m1);
    cudaGetSymbolAddress((void**)&p_m2,    g_m2);
    cudaGetSymbolAddress((void**)&p_h1,    g_h1);
    cudaGetSymbolAddress((void**)&p_h2,    g_h2);
    cudaGetSymbolAddress((void**)&p_maxlg, g_maxlg);
    cudaGetSymbolAddress((void**)&p_denlg, g_denlg);
    cudaGetSymbolAddress((void**)&p_maxg,  g_maxg);
    cudaGetSymbolAddress((void**)&p_deng,  g_deng);
    cudaGetSymbolAddress((void**)&p_acc1,  g_acc1);
    cudaGetSymbolAddress((void**)&p_acc2,  g_acc2);

    // ---- zero / init scratch ----
    cudaMemsetAsync(p_agg,   0, sizeof(float) * Ee * 128, 0);
    cudaMemsetAsync(p_cnt,   0, sizeof(float) * Ee, 0);
    cudaMemsetAsync(p_denlg, 0, sizeof(float) * Ee * 4, 0);
    cudaMemsetAsync(p_deng,  0, sizeof(float) * Nn * 4, 0);
    cudaMemsetAsync(p_acc1,  0, sizeof(float) * Ee * 256, 0);
    cudaMemsetAsync(p_acc2,  0, sizeof(float) * Ee * 256, 0);
    fill_kernel<<<(Ee * 4 + 255) / 256, 256>>>(p_maxlg, -INFINITY, Ee * 4);
    fill_kernel<<<(Nn * 4 + 255) / 256, 256>>>(p_maxg,  -INFINITY, Nn * 4);

    // ---- projection GEMMs (128x128 tiles) ----
    dim3 blk(256);
    dim3 grdE (2, (Ee  + 127) / 128);
    dim3 grdE2(2, (E2e + 127) / 128);
    dim3 grdN (2, (Nn  + 127) / 128);
    gemm128<<<grdE,  blk>>>(m_feats, W_lg_ni,  nullptr, p_lg_ni, Ee,  256, 128);
    gemm128<<<grdE,  blk>>>(m_feats, W_lg_nj,  nullptr, p_lg_nj, Ee,  256, 128);
    gemm128<<<grdE,  blk>>>(m_feats, W_g_fij,  nullptr, p_gfij,  Ee,  256, 128);
    gemm128<<<grdE2, blk>>>(x_feats, W_lg_fij, nullptr, p_lgfij, E2e, 256, 128);
    gemm128<<<grdN,  blk>>>(l_feats, W_g_ni,   nullptr, p_gni,   Nn,  256, 128);
    gemm128<<<grdN,  blk>>>(l_feats, W_g_nj,   nullptr, p_gnj,   Nn,  256, 128);

    // ---- segment mean of x_feats onto l-graph nodes; node-update inputs ----
    count_kernel<<<(E2e + 255) / 256, 256>>>(lgdst);
    scatter_x_kernel<<<(E2e * 128 + 255) / 256, 256>>>(lgdst, x_feats);
    build_m1_kernel<<<(Ee * 256 + 255) / 256, 256>>>(m_feats);
    build_m2_kernel<<<(Ee * 256 + 255) / 256, 256>>>(l_feats, m_feats, gsrc, gdst);
    gemm128<<<grdE, blk>>>(p_m1, W_lg_node, b_lg_node, p_h1, Ee, 256, 256);
    gemm128<<<grdE, blk>>>(p_m2, W_g_node,  b_g_node,  p_h2, Ee, 256, 256);

    // ---- attention scores + edge softmax ----
    lg_score_kernel<<<(E2e * 32 + 255) / 256, 256>>>(lgsrc, lgdst, lg_attn, bias_lg);
    g_score_kernel <<<(Ee  * 32 + 255) / 256, 256>>>(gsrc,  gdst,  g_attn,  bias_g);
    lg_exp_kernel<<<(E2e * 4 + 255) / 256, 256>>>(lgdst);
    g_exp_kernel <<<(Ee  * 4 + 255) / 256, 256>>>(gdst);
    ag_kernel    <<<(Ee  * 4 + 255) / 256, 256>>>(gdst);

    // ---- weighted message aggregation + epilogue ----
    msg_kernel<<<(E2e * 256 + 255) / 256, 256>>>(lgsrc, lgdst);
    final_kernel<<<(Ee * 64 + 255) / 256, 256>>>((float*)d_out);
}

// round 7
// speedup vs baseline: 1.4943x; 1.1798x over previous
#include <cuda_runtime.h>
#include <math.h>
#include <stdint.h>

// Problem constants (fixed by the dataset)
#define Nn   10000
#define Ee   160000
#define E2e  320000

// ---------------- scratch (device globals; no allocs allowed) ----------------
__device__ float g_lg_ni[Ee * 256];
__device__ float g_lg_nj[Ee * 256];
__device__ float g_gfij [Ee * 256];
__device__ float g_lgfij[E2e * 256];
__device__ float g_gni  [Nn * 256];
__device__ float g_gnj  [Nn * 256];
__device__ float g_agg  [Ee * 128];
__device__ float g_cnt  [Ee];
__device__ float g_m1   [Ee * 256];
__device__ float g_m2   [Ee * 256];
__device__ float g_h1   [Ee * 256];
__device__ float g_h2   [Ee * 256];
__device__ float g_slg  [E2e * 4];
__device__ float g_maxlg[Ee * 4];
__device__ float g_denlg[Ee * 4];
__device__ float g_sg   [Ee * 4];
__device__ float g_maxg [Nn * 4];
__device__ float g_deng [Nn * 4];
__device__ float g_ag   [Ee * 4];
__device__ float g_acc1 [Ee * 256];
__device__ float g_acc2 [Ee * 256];

__device__ __forceinline__ float lrelu(float x) { return x > 0.f ? x : 0.01f * x; }

__device__ __forceinline__ void atomicMaxF(float* addr, float val) {
    int* ia = (int*)addr;
    int old = __float_as_int(*addr);
    while (__int_as_float(old) < val) {
        int assumed = old;
        old = atomicCAS(ia, assumed, __float_as_int(val));
        if (old == assumed) break;
    }
}

__device__ __forceinline__ uint32_t cvt_tf32(float f) {
    uint32_t r;
    asm("cvt.rna.tf32.f32 %0, %1;" : "=r"(r) : "f"(f));
    return r;
}

// ========== tf32 mma.sync GEMM: C[M,256] = A[M,K] @ W[256,K]^T (+bias) ======
// BM=128, BN=128, BK=16, 256 threads (8 warps, 4x2), warp tile 32x64,
// m16n8k8 fragments, double-buffered smem with [k][m]/[k][n] layout, stride 136.
#define SST  136
#define BUFU (16 * SST)   // u32 per buffer per matrix

__global__ __launch_bounds__(256) void mmagemm(const float* __restrict__ A,
                                               const float* __restrict__ W,
                                               const float* __restrict__ bias,
                                               float* __restrict__ C,
                                               int M, int K)
{
    __shared__ uint32_t As[2 * BUFU];
    __shared__ uint32_t Ws[2 * BUFU];

    const int tid  = threadIdx.x;
    const int lane = tid & 31;
    const int warp = tid >> 5;
    const int gid  = lane >> 2;          // groupID 0..7
    const int tg   = lane & 3;           // thread-in-group 0..3
    const int mb   = (warp & 3) * 32;    // warp m base in tile
    const int nb   = (warp >> 2) * 64;   // warp n base in tile
    const int bm   = blockIdx.y * 128;
    const int bn   = blockIdx.x * 128;

    // staging: item idx in [0,512): r = idx & 127 (row), kq = idx >> 7 (f4 col)
    const int r_st = tid & 127;
    const int kqh  = tid >> 7;           // 0/1; item i adds 2*i
    const int arow = bm + r_st;
    const int wrow = bn + r_st;
    const float4 z4 = make_float4(0.f, 0.f, 0.f, 0.f);

    float acc[2][8][4];
#pragma unroll
    for (int a = 0; a < 2; a++)
#pragma unroll
        for (int b = 0; b < 8; b++)
#pragma unroll
            for (int c = 0; c < 4; c++) acc[a][b][c] = 0.f;

    float4 pa[2], pw[2];

    // ---- prologue: stage tile 0 ----
#pragma unroll
    for (int i = 0; i < 2; i++) {
        int kb = (kqh + 2 * i) * 4;
        pa[i] = (arow < M) ? *(const float4*)(A + (size_t)arow * K + kb) : z4;
        pw[i] = *(const float4*)(W + (size_t)wrow * K + kb);
    }
#pragma unroll
    for (int i = 0; i < 2; i++) {
        int kb = (kqh + 2 * i) * 4;
        As[(kb + 0) * SST + r_st] = cvt_tf32(pa[i].x);
        As[(kb + 1) * SST + r_st] = cvt_tf32(pa[i].y);
        As[(kb + 2) * SST + r_st] = cvt_tf32(pa[i].z);
        As[(kb + 3) * SST + r_st] = cvt_tf32(pa[i].w);
        Ws[(kb + 0) * SST + r_st] = cvt_tf32(pw[i].x);
        Ws[(kb + 1) * SST + r_st] = cvt_tf32(pw[i].y);
        Ws[(kb + 2) * SST + r_st] = cvt_tf32(pw[i].z);
        Ws[(kb + 3) * SST + r_st] = cvt_tf32(pw[i].w);
    }
    __syncthreads();

    const int nk = K >> 4;
    for (int t = 0; t < nk; t++) {
        const int cur = t & 1;
        if (t + 1 < nk) {
            const int k0 = (t + 1) << 4;
#pragma unroll
            for (int i = 0; i < 2; i++) {
                int kb = k0 + (kqh + 2 * i) * 4;
                pa[i] = (arow < M) ? *(const float4*)(A + (size_t)arow * K + kb) : z4;
                pw[i] = *(const float4*)(W + (size_t)wrow * K + kb);
            }
        }
        // ---- compute on buffer cur ----
        const uint32_t* Ab = As + cur * BUFU;
        const uint32_t* Wb = Ws + cur * BUFU;
#pragma unroll
        for (int kk = 0; kk < 16; kk += 8) {
            uint32_t af[2][4], bf[8][2];
#pragma unroll
            for (int mt = 0; mt < 2; mt++) {
                int m = mb + mt * 16 + gid;
                af[mt][0] = Ab[(kk + tg)     * SST + m];
                af[mt][1] = Ab[(kk + tg)     * SST + m + 8];
                af[mt][2] = Ab[(kk + tg + 4) * SST + m];
                af[mt][3] = Ab[(kk + tg + 4) * SST + m + 8];
            }
#pragma unroll
            for (int nt = 0; nt < 8; nt++) {
                int n = nb + nt * 8 + gid;
                bf[nt][0] = Wb[(kk + tg)     * SST + n];
                bf[nt][1] = Wb[(kk + tg + 4) * SST + n];
            }
#pragma unroll
            for (int mt = 0; mt < 2; mt++)
#pragma unroll
                for (int nt = 0; nt < 8; nt++)
                    asm volatile(
                        "mma.sync.aligned.m16n8k8.row.col.f32.tf32.tf32.f32 "
                        "{%0,%1,%2,%3}, {%4,%5,%6,%7}, {%8,%9}, {%0,%1,%2,%3};"
                        : "+f"(acc[mt][nt][0]), "+f"(acc[mt][nt][1]),
                          "+f"(acc[mt][nt][2]), "+f"(acc[mt][nt][3])
                        : "r"(af[mt][0]), "r"(af[mt][1]), "r"(af[mt][2]), "r"(af[mt][3]),
                          "r"(bf[nt][0]), "r"(bf[nt][1]));
        }
        if (t + 1 < nk) {
            const int nxt = cur ^ 1;
            uint32_t* An = As + nxt * BUFU;
            uint32_t* Wn = Ws + nxt * BUFU;
#pragma unroll
            for (int i = 0; i < 2; i++) {
                int kb = (kqh + 2 * i) * 4;
                An[(kb + 0) * SST + r_st] = cvt_tf32(pa[i].x);
                An[(kb + 1) * SST + r_st] = cvt_tf32(pa[i].y);
                An[(kb + 2) * SST + r_st] = cvt_tf32(pa[i].z);
                An[(kb + 3) * SST + r_st] = cvt_tf32(pa[i].w);
                Wn[(kb + 0) * SST + r_st] = cvt_tf32(pw[i].x);
                Wn[(kb + 1) * SST + r_st] = cvt_tf32(pw[i].y);
                Wn[(kb + 2) * SST + r_st] = cvt_tf32(pw[i].z);
                Wn[(kb + 3) * SST + r_st] = cvt_tf32(pw[i].w);
            }
            __syncthreads();
        }
    }

    // ---- epilogue ----
#pragma unroll
    for (int mt = 0; mt < 2; mt++) {
        int row0 = bm + mb + mt * 16 + gid;
#pragma unroll
        for (int nt = 0; nt < 8; nt++) {
            int col = bn + nb + nt * 8 + tg * 2;
            float bx = 0.f, by = 0.f;
            if (bias) { bx = bias[col]; by = bias[col + 1]; }
            if (row0 < M) {
                float2 v = make_float2(acc[mt][nt][0] + bx, acc[mt][nt][1] + by);
                *(float2*)(C + (size_t)row0 * 256 + col) = v;
            }
            if (row0 + 8 < M) {
                float2 v = make_float2(acc[mt][nt][2] + bx, acc[mt][nt][3] + by);
                *(float2*)(C + (size_t)(row0 + 8) * 256 + col) = v;
            }
        }
    }
}

// ---------------- small kernels ----------------
__global__ void fill_kernel(float* p, float v, int n) {
    int t = blockIdx.x * blockDim.x + threadIdx.x;
    if (t < n) p[t] = v;
}

__global__ void count_kernel(const int* __restrict__ lgdst) {
    int e2 = blockIdx.x * blockDim.x + threadIdx.x;
    if (e2 < E2e) atomicAdd(&g_cnt[lgdst[e2]], 1.f);
}

__global__ void scatter_x_kernel(const int* __restrict__ lgdst, const float* __restrict__ x) {
    int t = blockIdx.x * blockDim.x + threadIdx.x;
    if (t >= E2e * 128) return;
    int e2 = t >> 7, c = t & 127;
    atomicAdd(&g_agg[(size_t)lgdst[e2] * 128 + c], x[t]);
}

__global__ void build_m1_kernel(const float* __restrict__ m_feats) {
    int t = blockIdx.x * blockDim.x + threadIdx.x;
    if (t >= Ee * 256) return;
    int e = t >> 8, c = t & 255;
    float v;
    if (c < 128) v = m_feats[(size_t)e * 128 + c];
    else         v = g_agg[(size_t)e * 128 + (c - 128)] / fmaxf(g_cnt[e], 1.f);
    g_m1[t] = v;
}

__global__ void build_m2_kernel(const float* __restrict__ l_feats,
                                const float* __restrict__ m_feats,
                                const int* __restrict__ gsrc,
                                const int* __restrict__ gdst) {
    int t = blockIdx.x * blockDim.x + threadIdx.x;
    if (t >= Ee * 256) return;
    int e = t >> 8, c = t & 255;
    float v;
    if (c < 128) v = l_feats[(size_t)gsrc[e] * 128 + c] + l_feats[(size_t)gdst[e] * 128 + c];
    else         v = m_feats[(size_t)e * 128 + (c - 128)];
    g_m2[t] = v;
}

// line-graph attention scores: one warp per l-graph edge
__global__ void lg_score_kernel(const int* __restrict__ src, const int* __restrict__ dst,
                                const float* __restrict__ attn, const float* __restrict__ bias) {
    int w = (blockIdx.x * blockDim.x + threadIdx.x) >> 5;
    if (w >= E2e) return;
    int lane = threadIdx.x & 31;
    int s = src[w], d = dst[w];
    const float* ni  = g_lg_ni + (size_t)s * 256;
    const float* nj  = g_lg_nj + (size_t)d * 256;
    const float* fij = g_lgfij + (size_t)w * 256;
    float p[4] = {0.f, 0.f, 0.f, 0.f};
#pragma unroll
    for (int j = 0; j < 8; j++) {
        int i = lane + 32 * j;
        float v = lrelu(ni[i] + nj[i] + fij[i] + bias[i]);
        p[j >> 1] += v * attn[i];
    }
#pragma unroll
    for (int h = 0; h < 4; h++)
#pragma unroll
        for (int o = 16; o > 0; o >>= 1)
            p[h] += __shfl_xor_sync(0xffffffffu, p[h], o);
    if (lane == 0) {
#pragma unroll
        for (int h = 0; h < 4; h++) {
            g_slg[(size_t)w * 4 + h] = p[h];
            atomicMaxF(&g_maxlg[(size_t)d * 4 + h], p[h]);
        }
    }
}

// base-graph attention scores: one warp per graph edge
__global__ void g_score_kernel(const int* __restrict__ src, const int* __restrict__ dst,
                               const float* __restrict__ attn, const float* __restrict__ bias) {
    int w = (blockIdx.x * blockDim.x + threadIdx.x) >> 5;
    if (w >= Ee) return;
    int lane = threadIdx.x & 31;
    int s = src[w], d = dst[w];
    const float* ni  = g_gni  + (size_t)s * 256;
    const float* nj  = g_gnj  + (size_t)d * 256;
    const float* fij = g_gfij + (size_t)w * 256;
    float p[4] = {0.f, 0.f, 0.f, 0.f};
#pragma unroll
    for (int j = 0; j < 8; j++) {
        int i = lane + 32 * j;
        float v = lrelu(ni[i] + nj[i] + fij[i] + bias[i]);
        p[j >> 1] += v * attn[i];
    }
#pragma unroll
    for (int h = 0; h < 4; h++)
#pragma unroll
        for (int o = 16; o > 0; o >>= 1)
            p[h] += __shfl_xor_sync(0xffffffffu, p[h], o);
    if (lane == 0) {
#pragma unroll
        for (int h = 0; h < 4; h++) {
            g_sg[(size_t)w * 4 + h] = p[h];
            atomicMaxF(&g_maxg[(size_t)d * 4 + h], p[h]);
        }
    }
}

__global__ void lg_exp_kernel(const int* __restrict__ dst) {
    int t = blockIdx.x * blockDim.x + threadIdx.x;
    if (t >= E2e * 4) return;
    int e2 = t >> 2, h = t & 3;
    int d = dst[e2];
    float v = expf(g_slg[t] - g_maxlg[(size_t)d * 4 + h]);
    g_slg[t] = v;
    atomicAdd(&g_denlg[(size_t)d * 4 + h], v);
}

__global__ void g_exp_kernel(const int* __restrict__ dst) {
    int t = blockIdx.x * blockDim.x + threadIdx.x;
    if (t >= Ee * 4) return;
    int e = t >> 2, h = t & 3;
    int d = dst[e];
    float v = expf(g_sg[t] - g_maxg[(size_t)d * 4 + h]);
    g_sg[t] = v;
    atomicAdd(&g_deng[(size_t)d * 4 + h], v);
}

__global__ void ag_kernel(const int* __restrict__ gdst) {
    int t = blockIdx.x * blockDim.x + threadIdx.x;
    if (t >= Ee * 4) return;
    int e = t >> 2, h = t & 3;
    g_ag[t] = g_sg[t] / g_deng[(size_t)gdst[e] * 4 + h];
}

__global__ void msg_kernel(const int* __restrict__ src, const int* __restrict__ dst) {
    int t = blockIdx.x * blockDim.x + threadIdx.x;
    if (t >= E2e * 256) return;
    int e2 = t >> 8, c = t & 255, h = c >> 6;
    int s = src[e2], d = dst[e2];
    float alg = g_slg[(size_t)e2 * 4 + h] / g_denlg[(size_t)d * 4 + h];
    atomicAdd(&g_acc1[(size_t)d * 256 + c], g_h1[(size_t)s * 256 + c] * alg);
    atomicAdd(&g_acc2[(size_t)d * 256 + c], g_h2[(size_t)s * 256 + c] * g_ag[(size_t)d * 4 + h]);
}

__global__ void final_kernel(float* __restrict__ out) {
    int t = blockIdx.x * blockDim.x + threadIdx.x;
    if (t >= Ee * 64) return;
    int e = t >> 6, c = t & 63;
    float o = 0.f;
#pragma unroll
    for (int h = 0; h < 4; h++) {
        o += lrelu(g_acc1[(size_t)e * 256 + h * 64 + c]);
        o += lrelu(g_acc2[(size_t)e * 256 + h * 64 + c]);
    }
    out[t] = o;
}

// ---------------- host launch ----------------
extern "C" void kernel_launch(void* const* d_in, const int* in_sizes, int n_in,
                              void* d_out, int out_size)
{
    const float *l_feats = (const float*)d_in[0];
    const float *m_feats = (const float*)d_in[1];
    const float *x_feats = (const float*)d_in[2];
    const float *W_lg_node, *b_lg_node, *W_lg_ni, *W_lg_fij, *W_lg_nj, *lg_attn, *bias_lg;
    const float *W_g_node, *b_g_node, *W_g_ni, *W_g_fij, *W_g_nj, *g_attn, *bias_g;
    const int *gsrc, *gdst, *lgsrc, *lgdst;

    if (in_sizes[3] == Ee) {  // setup_inputs dict order
        gsrc = (const int*)d_in[3];  gdst = (const int*)d_in[4];
        lgsrc = (const int*)d_in[5]; lgdst = (const int*)d_in[6];
        W_lg_node = (const float*)d_in[7];  b_lg_node = (const float*)d_in[8];
        W_lg_ni   = (const float*)d_in[9];  W_lg_fij  = (const float*)d_in[10];
        W_lg_nj   = (const float*)d_in[11]; lg_attn   = (const float*)d_in[12];
        bias_lg   = (const float*)d_in[13];
        W_g_node  = (const float*)d_in[14]; b_g_node  = (const float*)d_in[15];
        W_g_ni    = (const float*)d_in[16]; W_g_fij   = (const float*)d_in[17];
        W_g_nj    = (const float*)d_in[18]; g_attn    = (const float*)d_in[19];
        bias_g    = (const float*)d_in[20];
    } else {                  // reference() signature order
        W_lg_node = (const float*)d_in[3];  b_lg_node = (const float*)d_in[4];
        W_lg_ni   = (const float*)d_in[5];  W_lg_fij  = (const float*)d_in[6];
        W_lg_nj   = (const float*)d_in[7];  lg_attn   = (const float*)d_in[8];
        bias_lg   = (const float*)d_in[9];
        W_g_node  = (const float*)d_in[10]; b_g_node  = (const float*)d_in[11];
        W_g_ni    = (const float*)d_in[12]; W_g_fij   = (const float*)d_in[13];
        W_g_nj    = (const float*)d_in[14]; g_attn    = (const float*)d_in[15];
        bias_g    = (const float*)d_in[16];
        gsrc  = (const int*)d_in[17]; gdst  = (const int*)d_in[18];
        lgsrc = (const int*)d_in[19]; lgdst = (const int*)d_in[20];
    }

    float *p_lg_ni, *p_lg_nj, *p_gfij, *p_lgfij, *p_gni, *p_gnj;
    float *p_agg, *p_cnt, *p_m1, *p_m2, *p_h1, *p_h2;
    float *p_maxlg, *p_denlg, *p_maxg, *p_deng, *p_acc1, *p_acc2;
    cudaGetSymbolAddress((void**)&p_lg_ni, g_lg_ni);
    cudaGetSymbolAddress((void**)&p_lg_nj, g_lg_nj);
    cudaGetSymbolAddress((void**)&p_gfij,  g_gfij);
    cudaGetSymbolAddress((void**)&p_lgfij, g_lgfij);
    cudaGetSymbolAddress((void**)&p_gni,   g_gni);
    cudaGetSymbolAddress((void**)&p_gnj,   g_gnj);
    cudaGetSymbolAddress((void**)&p_agg,   g_agg);
    cudaGetSymbolAddress((void**)&p_cnt,   g_cnt);
    cudaGetSymbolAddress((void**)&p_m1,    g_m1);
    cudaGetSymbolAddress((void**)&p_m2,    g_m2);
    cudaGetSymbolAddress((void**)&p_h1,    g_h1);
    cudaGetSymbolAddress((void**)&p_h2,    g_h2);
    cudaGetSymbolAddress((void**)&p_maxlg, g_maxlg);
    cudaGetSymbolAddress((void**)&p_denlg, g_denlg);
    cudaGetSymbolAddress((void**)&p_maxg,  g_maxg);
    cudaGetSymbolAddress((void**)&p_deng,  g_deng);
    cudaGetSymbolAddress((void**)&p_acc1,  g_acc1);
    cudaGetSymbolAddress((void**)&p_acc2,  g_acc2);

    // ---- zero / init scratch ----
    cudaMemsetAsync(p_agg,   0, sizeof(float) * Ee * 128, 0);
    cudaMemsetAsync(p_cnt,   0, sizeof(float) * Ee, 0);
    cudaMemsetAsync(p_denlg, 0, sizeof(float) * Ee * 4, 0);
    cudaMemsetAsync(p_deng,  0, sizeof(float) * Nn * 4, 0);
    cudaMemsetAsync(p_acc1,  0, sizeof(float) * Ee * 256, 0);
    cudaMemsetAsync(p_acc2,  0, sizeof(float) * Ee * 256, 0);
    fill_kernel<<<(Ee * 4 + 255) / 256, 256>>>(p_maxlg, -INFINITY, Ee * 4);
    fill_kernel<<<(Nn * 4 + 255) / 256, 256>>>(p_maxg,  -INFINITY, Nn * 4);

    // ---- projection GEMMs (tf32 mma.sync) ----
    dim3 blk(256);
    dim3 grdE (2, (Ee  + 127) / 128);
    dim3 grdE2(2, (E2e + 127) / 128);
    dim3 grdN (2, (Nn  + 127) / 128);
    mmagemm<<<grdE,  blk>>>(m_feats, W_lg_ni,  nullptr, p_lg_ni, Ee,  128);
    mmagemm<<<grdE,  blk>>>(m_feats, W_lg_nj,  nullptr, p_lg_nj, Ee,  128);
    mmagemm<<<grdE,  blk>>>(m_feats, W_g_fij,  nullptr, p_gfij,  Ee,  128);
    mmagemm<<<grdE2, blk>>>(x_feats, W_lg_fij, nullptr, p_lgfij, E2e, 128);
    mmagemm<<<grdN,  blk>>>(l_feats, W_g_ni,   nullptr, p_gni,   Nn,  128);
    mmagemm<<<grdN,  blk>>>(l_feats, W_g_nj,   nullptr, p_gnj,   Nn,  128);

    // ---- segment mean of x_feats onto l-graph nodes; node-update inputs ----
    count_kernel<<<(E2e + 255) / 256, 256>>>(lgdst);
    scatter_x_kernel<<<(E2e * 128 + 255) / 256, 256>>>(lgdst, x_feats);
    build_m1_kernel<<<(Ee * 256 + 255) / 256, 256>>>(m_feats);
    build_m2_kernel<<<(Ee * 256 + 255) / 256, 256>>>(l_feats, m_feats, gsrc, gdst);
    mmagemm<<<grdE, blk>>>(p_m1, W_lg_node, b_lg_node, p_h1, Ee, 256);
    mmagemm<<<grdE, blk>>>(p_m2, W_g_node,  b_g_node,  p_h2, Ee, 256);

    // ---- attention scores + edge softmax ----
    lg_score_kernel<<<(E2e * 32 + 255) / 256, 256>>>(lgsrc, lgdst, lg_attn, bias_lg);
    g_score_kernel <<<(Ee  * 32 + 255) / 256, 256>>>(gsrc,  gdst,  g_attn,  bias_g);
    lg_exp_kernel<<<(E2e * 4 + 255) / 256, 256>>>(lgdst);
    g_exp_kernel <<<(Ee  * 4 + 255) / 256, 256>>>(gdst);
    ag_kernel    <<<(Ee  * 4 + 255) / 256, 256>>>(gdst);

    // ---- weighted message aggregation + epilogue ----
    msg_kernel<<<(E2e * 256 + 255) / 256, 256>>>(lgsrc, lgdst);
    final_kernel<<<(Ee * 64 + 255) / 256, 256>>>((float*)d_out);
}

// round 8
// speedup vs baseline: 1.7122x; 1.1458x over previous
#include <cuda_runtime.h>
#include <math.h>
#include <stdint.h>

// Problem constants (fixed by the dataset)
#define Nn   10000
#define Ee   160000
#define E2e  320000

// ---------------- scratch (device globals; no allocs allowed) ----------------
__device__ float g_lg_ni[Ee * 256];
__device__ float g_lg_nj[Ee * 256];
__device__ float g_gfij [Ee * 256];
__device__ float g_lgfij[E2e * 256];
__device__ float g_gni  [Nn * 256];
__device__ float g_gnj  [Nn * 256];
__device__ float g_m1   [Ee * 256];
__device__ float g_m2   [Ee * 256];
__device__ float g_h1   [Ee * 256];
__device__ float g_h2   [Ee * 256];
__device__ float g_slg  [E2e * 4];
__device__ float g_maxlg[Ee * 4];
__device__ float g_denlg[Ee * 4];
__device__ float g_sg   [Ee * 4];
__device__ float g_maxg [Nn * 4];
__device__ float g_deng [Nn * 4];
__device__ float g_ag   [Ee * 4];
// CSR of lg_dst
__device__ int   g_rcnt  [Ee];
__device__ int   g_fill  [Ee];
__device__ int   g_rowptr[Ee + 1];
__device__ int   g_eidx  [E2e];

__device__ __forceinline__ float lrelu(float x) { return x > 0.f ? x : 0.01f * x; }

__device__ __forceinline__ void atomicMaxF(float* addr, float val) {
    int* ia = (int*)addr;
    int old = __float_as_int(*addr);
    while (__int_as_float(old) < val) {
        int assumed = old;
        old = atomicCAS(ia, assumed, __float_as_int(val));
        if (old == assumed) break;
    }
}

__device__ __forceinline__ uint32_t cvt_tf32(float f) {
    uint32_t r;
    asm("cvt.rna.tf32.f32 %0, %1;" : "=r"(r) : "f"(f));
    return r;
}

// ========== tf32 mma.sync GEMM: C[M,256] = A[M,K] @ W[256,K]^T (+bias) ======
#define SST  136
#define BUFU (16 * SST)

__global__ __launch_bounds__(256) void mmagemm(const float* __restrict__ A,
                                               const float* __restrict__ W,
                                               const float* __restrict__ bias,
                                               float* __restrict__ C,
                                               int M, int K)
{
    __shared__ uint32_t As[2 * BUFU];
    __shared__ uint32_t Ws[2 * BUFU];

    const int tid  = threadIdx.x;
    const int lane = tid & 31;
    const int warp = tid >> 5;
    const int gid  = lane >> 2;
    const int tg   = lane & 3;
    const int mb   = (warp & 3) * 32;
    const int nb   = (warp >> 2) * 64;
    const int bm   = blockIdx.y * 128;
    const int bn   = blockIdx.x * 128;

    const int r_st = tid & 127;
    const int kqh  = tid >> 7;
    const int arow = bm + r_st;
    const int wrow = bn + r_st;
    const float4 z4 = make_float4(0.f, 0.f, 0.f, 0.f);

    float acc[2][8][4];
#pragma unroll
    for (int a = 0; a < 2; a++)
#pragma unroll
        for (int b = 0; b < 8; b++)
#pragma unroll
            for (int c = 0; c < 4; c++) acc[a][b][c] = 0.f;

    float4 pa[2], pw[2];

#pragma unroll
    for (int i = 0; i < 2; i++) {
        int kb = (kqh + 2 * i) * 4;
        pa[i] = (arow < M) ? *(const float4*)(A + (size_t)arow * K + kb) : z4;
        pw[i] = *(const float4*)(W + (size_t)wrow * K + kb);
    }
#pragma unroll
    for (int i = 0; i < 2; i++) {
        int kb = (kqh + 2 * i) * 4;
        As[(kb + 0) * SST + r_st] = cvt_tf32(pa[i].x);
        As[(kb + 1) * SST + r_st] = cvt_tf32(pa[i].y);
        As[(kb + 2) * SST + r_st] = cvt_tf32(pa[i].z);
        As[(kb + 3) * SST + r_st] = cvt_tf32(pa[i].w);
        Ws[(kb + 0) * SST + r_st] = cvt_tf32(pw[i].x);
        Ws[(kb + 1) * SST + r_st] = cvt_tf32(pw[i].y);
        Ws[(kb + 2) * SST + r_st] = cvt_tf32(pw[i].z);
        Ws[(kb + 3) * SST + r_st] = cvt_tf32(pw[i].w);
    }
    __syncthreads();

    const int nk = K >> 4;
    for (int t = 0; t < nk; t++) {
        const int cur = t & 1;
        if (t + 1 < nk) {
            const int k0 = (t + 1) << 4;
#pragma unroll
            for (int i = 0; i < 2; i++) {
                int kb = k0 + (kqh + 2 * i) * 4;
                pa[i] = (arow < M) ? *(const float4*)(A + (size_t)arow * K + kb) : z4;
                pw[i] = *(const float4*)(W + (size_t)wrow * K + kb);
            }
        }
        const uint32_t* Ab = As + cur * BUFU;
        const uint32_t* Wb = Ws + cur * BUFU;
#pragma unroll
        for (int kk = 0; kk < 16; kk += 8) {
            uint32_t af[2][4], bf[8][2];
#pragma unroll
            for (int mt = 0; mt < 2; mt++) {
                int m = mb + mt * 16 + gid;
                af[mt][0] = Ab[(kk + tg)     * SST + m];
                af[mt][1] = Ab[(kk + tg)     * SST + m + 8];
                af[mt][2] = Ab[(kk + tg + 4) * SST + m];
                af[mt][3] = Ab[(kk + tg + 4) * SST + m + 8];
            }
#pragma unroll
            for (int nt = 0; nt < 8; nt++) {
                int n = nb + nt * 8 + gid;
                bf[nt][0] = Wb[(kk + tg)     * SST + n];
                bf[nt][1] = Wb[(kk + tg + 4) * SST + n];
            }
#pragma unroll
            for (int mt = 0; mt < 2; mt++)
#pragma unroll
                for (int nt = 0; nt < 8; nt++)
                    asm volatile(
                        "mma.sync.aligned.m16n8k8.row.col.f32.tf32.tf32.f32 "
                        "{%0,%1,%2,%3}, {%4,%5,%6,%7}, {%8,%9}, {%0,%1,%2,%3};"
                        : "+f"(acc[mt][nt][0]), "+f"(acc[mt][nt][1]),
                          "+f"(acc[mt][nt][2]), "+f"(acc[mt][nt][3])
                        : "r"(af[mt][0]), "r"(af[mt][1]), "r"(af[mt][2]), "r"(af[mt][3]),
                          "r"(bf[nt][0]), "r"(bf[nt][1]));
        }
        if (t + 1 < nk) {
            const int nxt = cur ^ 1;
            uint32_t* An = As + nxt * BUFU;
            uint32_t* Wn = Ws + nxt * BUFU;
#pragma unroll
            for (int i = 0; i < 2; i++) {
                int kb = (kqh + 2 * i) * 4;
                An[(kb + 0) * SST + r_st] = cvt_tf32(pa[i].x);
                An[(kb + 1) * SST + r_st] = cvt_tf32(pa[i].y);
                An[(kb + 2) * SST + r_st] = cvt_tf32(pa[i].z);
                An[(kb + 3) * SST + r_st] = cvt_tf32(pa[i].w);
                Wn[(kb + 0) * SST + r_st] = cvt_tf32(pw[i].x);
                Wn[(kb + 1) * SST + r_st] = cvt_tf32(pw[i].y);
                Wn[(kb + 2) * SST + r_st] = cvt_tf32(pw[i].z);
                Wn[(kb + 3) * SST + r_st] = cvt_tf32(pw[i].w);
            }
            __syncthreads();
        }
    }

#pragma unroll
    for (int mt = 0; mt < 2; mt++) {
        int row0 = bm + mb + mt * 16 + gid;
#pragma unroll
        for (int nt = 0; nt < 8; nt++) {
            int col = bn + nb + nt * 8 + tg * 2;
            float bx = 0.f, by = 0.f;
            if (bias) { bx = bias[col]; by = bias[col + 1]; }
            if (row0 < M) {
                float2 v = make_float2(acc[mt][nt][0] + bx, acc[mt][nt][1] + by);
                *(float2*)(C + (size_t)row0 * 256 + col) = v;
            }
            if (row0 + 8 < M) {
                float2 v = make_float2(acc[mt][nt][2] + bx, acc[mt][nt][3] + by);
                *(float2*)(C + (size_t)(row0 + 8) * 256 + col) = v;
            }
        }
    }
}

// ---------------- CSR build ----------------
__global__ void hist_kernel(const int* __restrict__ lgdst) {
    int e2 = blockIdx.x * blockDim.x + threadIdx.x;
    if (e2 < E2e) atomicAdd(&g_rcnt[lgdst[e2]], 1);
}

__global__ __launch_bounds__(1024) void scan_kernel() {
    __shared__ int part[1024];
    const int CH = (Ee + 1023) / 1024;   // 157
    const int t = threadIdx.x;
    const int base = t * CH;
    int s = 0;
    for (int i = 0; i < CH; i++) {
        int j = base + i;
        if (j < Ee) s += g_rcnt[j];
    }
    part[t] = s;
    __syncthreads();
    for (int off = 1; off < 1024; off <<= 1) {
        int v = (t >= off) ? part[t - off] : 0;
        __syncthreads();
        part[t] += v;
        __syncthreads();
    }
    int run = (t == 0) ? 0 : part[t - 1];
    for (int i = 0; i < CH; i++) {
        int j = base + i;
        if (j < Ee) { g_rowptr[j] = run; run += g_rcnt[j]; }
    }
    if (t == 1023) g_rowptr[Ee] = run;
}

__global__ void scatter_csr_kernel(const int* __restrict__ lgdst) {
    int e2 = blockIdx.x * blockDim.x + threadIdx.x;
    if (e2 >= E2e) return;
    int d = lgdst[e2];
    int p = g_rowptr[d] + atomicAdd(&g_fill[d], 1);
    g_eidx[p] = e2;
}

// ---------------- small kernels ----------------
__global__ void fill_kernel(float* p, float v, int n) {
    int t = blockIdx.x * blockDim.x + threadIdx.x;
    if (t < n) p[t] = v;
}

// per dst l-node: mean-aggregate x_feats of incoming edges; build m1 row
__global__ __launch_bounds__(128) void agg_m1_kernel(const float* __restrict__ m_feats,
                                                     const float* __restrict__ x_feats) {
    int e = blockIdx.x;
    int c = threadIdx.x;        // 0..127
    int r0 = g_rowptr[e], r1 = g_rowptr[e + 1];
    float s = 0.f;
    for (int i = r0; i < r1; i++)
        s += x_feats[(size_t)g_eidx[i] * 128 + c];
    float inv = 1.f / fmaxf((float)(r1 - r0), 1.f);
    g_m1[(size_t)e * 256 + c]       = m_feats[(size_t)e * 128 + c];
    g_m1[(size_t)e * 256 + 128 + c] = s * inv;
}

__global__ void build_m2_kernel(const float* __restrict__ l_feats,
                                const float* __restrict__ m_feats,
                                const int* __restrict__ gsrc,
                                const int* __restrict__ gdst) {
    int t = blockIdx.x * blockDim.x + threadIdx.x;
    if (t >= Ee * 256) return;
    int e = t >> 8, c = t & 255;
    float v;
    if (c < 128) v = l_feats[(size_t)gsrc[e] * 128 + c] + l_feats[(size_t)gdst[e] * 128 + c];
    else         v = m_feats[(size_t)e * 128 + (c - 128)];
    g_m2[t] = v;
}

// line-graph attention scores (raw; softmax done by CSR pass)
__global__ void lg_score_kernel(const int* __restrict__ src, const int* __restrict__ dst,
                                const float* __restrict__ attn, const float* __restrict__ bias) {
    int w = (blockIdx.x * blockDim.x + threadIdx.x) >> 5;
    if (w >= E2e) return;
    int lane = threadIdx.x & 31;
    int s = src[w], d = dst[w];
    const float* ni  = g_lg_ni + (size_t)s * 256;
    const float* nj  = g_lg_nj + (size_t)d * 256;
    const float* fij = g_lgfij + (size_t)w * 256;
    float p[4] = {0.f, 0.f, 0.f, 0.f};
#pragma unroll
    for (int j = 0; j < 8; j++) {
        int i = lane + 32 * j;
        float v = lrelu(ni[i] + nj[i] + fij[i] + bias[i]);
        p[j >> 1] += v * attn[i];
    }
#pragma unroll
    for (int h = 0; h < 4; h++)
#pragma unroll
        for (int o = 16; o > 0; o >>= 1)
            p[h] += __shfl_xor_sync(0xffffffffu, p[h], o);
    if (lane == 0) {
#pragma unroll
        for (int h = 0; h < 4; h++)
            g_slg[(size_t)w * 4 + h] = p[h];
    }
}

// CSR segmented softmax stats per (dst l-node, head)
__global__ void lgsoftmax_kernel() {
    int t = blockIdx.x * blockDim.x + threadIdx.x;
    if (t >= Ee * 4) return;
    int e = t >> 2, h = t & 3;
    int r0 = g_rowptr[e], r1 = g_rowptr[e + 1];
    float m = -INFINITY;
    for (int i = r0; i < r1; i++)
        m = fmaxf(m, g_slg[(size_t)g_eidx[i] * 4 + h]);
    float den = 0.f;
    for (int i = r0; i < r1; i++)
        den += expf(g_slg[(size_t)g_eidx[i] * 4 + h] - m);
    g_maxlg[t] = m;
    g_denlg[t] = (r1 > r0) ? den : 1.f;
}

// normalize lg scores in place: slg <- a_lg
__global__ void lgnorm_kernel(const int* __restrict__ dst) {
    int t = blockIdx.x * blockDim.x + threadIdx.x;
    if (t >= E2e * 4) return;
    int e2 = t >> 2, h = t & 3;
    int d = dst[e2];
    g_slg[t] = expf(g_slg[t] - g_maxlg[(size_t)d * 4 + h]) / g_denlg[(size_t)d * 4 + h];
}

// base-graph attention scores: one warp per graph edge (atomic max over nodes)
__global__ void g_score_kernel(const int* __restrict__ src, const int* __restrict__ dst,
                               const float* __restrict__ attn, const float* __restrict__ bias) {
    int w = (blockIdx.x * blockDim.x + threadIdx.x) >> 5;
    if (w >= Ee) return;
    int lane = threadIdx.x & 31;
    int s = src[w], d = dst[w];
    const float* ni  = g_gni  + (size_t)s * 256;
    const float* nj  = g_gnj  + (size_t)d * 256;
    const float* fij = g_gfij + (size_t)w * 256;
    float p[4] = {0.f, 0.f, 0.f, 0.f};
#pragma unroll
    for (int j = 0; j < 8; j++) {
        int i = lane + 32 * j;
        float v = lrelu(ni[i] + nj[i] + fij[i] + bias[i]);
        p[j >> 1] += v * attn[i];
    }
#pragma unroll
    for (int h = 0; h < 4; h++)
#pragma unroll
        for (int o = 16; o > 0; o >>= 1)
            p[h] += __shfl_xor_sync(0xffffffffu, p[h], o);
    if (lane == 0) {
#pragma unroll
        for (int h = 0; h < 4; h++) {
            g_sg[(size_t)w * 4 + h] = p[h];
            atomicMaxF(&g_maxg[(size_t)d * 4 + h], p[h]);
        }
    }
}

__global__ void g_exp_kernel(const int* __restrict__ dst) {
    int t = blockIdx.x * blockDim.x + threadIdx.x;
    if (t >= Ee * 4) return;
    int e = t >> 2, h = t & 3;
    int d = dst[e];
    float v = expf(g_sg[t] - g_maxg[(size_t)d * 4 + h]);
    g_sg[t] = v;
    atomicAdd(&g_deng[(size_t)d * 4 + h], v);
}

__global__ void ag_kernel(const int* __restrict__ gdst) {
    int t = blockIdx.x * blockDim.x + threadIdx.x;
    if (t >= Ee * 4) return;
    int e = t >> 2, h = t & 3;
    g_ag[t] = g_sg[t] / g_deng[(size_t)gdst[e] * 4 + h];
}

// fused CSR gather of both message branches + lrelu head-sum epilogue
__global__ __launch_bounds__(256) void gather_final_kernel(const int* __restrict__ lgsrc,
                                                           float* __restrict__ out) {
    __shared__ float red[256];
    int e = blockIdx.x;
    int c = threadIdx.x;
    int h = c >> 6;
    int r0 = g_rowptr[e], r1 = g_rowptr[e + 1];
    float agh = g_ag[(size_t)e * 4 + h];
    float a1 = 0.f, a2 = 0.f;
    for (int i = r0; i < r1; i++) {
        int e2 = g_eidx[i];
        int s = lgsrc[e2];
        float alg = g_slg[(size_t)e2 * 4 + h];
        a1 += g_h1[(size_t)s * 256 + c] * alg;
        a2 += g_h2[(size_t)s * 256 + c] * agh;
    }
    red[c] = lrelu(a1) + lrelu(a2);
    __syncthreads();
    if (c < 64)
        out[(size_t)e * 64 + c] = red[c] + red[c + 64] + red[c + 128] + red[c + 192];
}

// ---------------- host launch ----------------
extern "C" void kernel_launch(void* const* d_in, const int* in_sizes, int n_in,
                              void* d_out, int out_size)
{
    const float *l_feats = (const float*)d_in[0];
    const float *m_feats = (const float*)d_in[1];
    const float *x_feats = (const float*)d_in[2];
    const float *W_lg_node, *b_lg_node, *W_lg_ni, *W_lg_fij, *W_lg_nj, *lg_attn, *bias_lg;
    const float *W_g_node, *b_g_node, *W_g_ni, *W_g_fij, *W_g_nj, *g_attn, *bias_g;
    const int *gsrc, *gdst, *lgsrc, *lgdst;

    if (in_sizes[3] == Ee) {  // setup_inputs dict order
        gsrc = (const int*)d_in[3];  gdst = (const int*)d_in[4];
        lgsrc = (const int*)d_in[5]; lgdst = (const int*)d_in[6];
        W_lg_node = (const float*)d_in[7];  b_lg_node = (const float*)d_in[8];
        W_lg_ni   = (const float*)d_in[9];  W_lg_fij  = (const float*)d_in[10];
        W_lg_nj   = (const float*)d_in[11]; lg_attn   = (const float*)d_in[12];
        bias_lg   = (const float*)d_in[13];
        W_g_node  = (const float*)d_in[14]; b_g_node  = (const float*)d_in[15];
        W_g_ni    = (const float*)d_in[16]; W_g_fij   = (const float*)d_in[17];
        W_g_nj    = (const float*)d_in[18]; g_attn    = (const float*)d_in[19];
        bias_g    = (const float*)d_in[20];
    } else {                  // reference() signature order
        W_lg_node = (const float*)d_in[3];  b_lg_node = (const float*)d_in[4];
        W_lg_ni   = (const float*)d_in[5];  W_lg_fij  = (const float*)d_in[6];
        W_lg_nj   = (const float*)d_in[7];  lg_attn   = (const float*)d_in[8];
        bias_lg   = (const float*)d_in[9];
        W_g_node  = (const float*)d_in[10]; b_g_node  = (const float*)d_in[11];
        W_g_ni    = (const float*)d_in[12]; W_g_fij   = (const float*)d_in[13];
        W_g_nj    = (const float*)d_in[14]; g_attn    = (const float*)d_in[15];
        bias_g    = (const float*)d_in[16];
        gsrc  = (const int*)d_in[17]; gdst  = (const int*)d_in[18];
        lgsrc = (const int*)d_in[19]; lgdst = (const int*)d_in[20];
    }

    float *p_lg_ni, *p_lg_nj, *p_gfij, *p_lgfij, *p_gni, *p_gnj;
    float *p_m1, *p_m2, *p_h1, *p_h2, *p_maxg, *p_deng;
    int *p_rcnt, *p_fill;
    cudaGetSymbolAddress((void**)&p_lg_ni, g_lg_ni);
    cudaGetSymbolAddress((void**)&p_lg_nj, g_lg_nj);
    cudaGetSymbolAddress((void**)&p_gfij,  g_gfij);
    cudaGetSymbolAddress((void**)&p_lgfij, g_lgfij);
    cudaGetSymbolAddress((void**)&p_gni,   g_gni);
    cudaGetSymbolAddress((void**)&p_gnj,   g_gnj);
    cudaGetSymbolAddress((void**)&p_m1,    g_m1);
    cudaGetSymbolAddress((void**)&p_m2,    g_m2);
    cudaGetSymbolAddress((void**)&p_h1,    g_h1);
    cudaGetSymbolAddress((void**)&p_h2,    g_h2);
    cudaGetSymbolAddress((void**)&p_maxg,  g_maxg);
    cudaGetSymbolAddress((void**)&p_deng,  g_deng);
    cudaGetSymbolAddress((void**)&p_rcnt,  g_rcnt);
    cudaGetSymbolAddress((void**)&p_fill,  g_fill);

    // ---- zero / init scratch ----
    cudaMemsetAsync(p_rcnt, 0, sizeof(int) * Ee, 0);
    cudaMemsetAsync(p_fill, 0, sizeof(int) * Ee, 0);
    cudaMemsetAsync(p_deng, 0, sizeof(float) * Nn * 4, 0);
    fill_kernel<<<(Nn * 4 + 255) / 256, 256>>>(p_maxg, -INFINITY, Nn * 4);

    // ---- CSR build (independent of GEMMs) ----
    hist_kernel<<<(E2e + 255) / 256, 256>>>(lgdst);
    scan_kernel<<<1, 1024>>>();
    scatter_csr_kernel<<<(E2e + 255) / 256, 256>>>(lgdst);

    // ---- projection GEMMs (tf32 mma.sync) ----
    dim3 blk(256);
    dim3 grdE (2, (Ee  + 127) / 128);
    dim3 grdE2(2, (E2e + 127) / 128);
    dim3 grdN (2, (Nn  + 127) / 128);
    mmagemm<<<grdE,  blk>>>(m_feats, W_lg_ni,  nullptr, p_lg_ni, Ee,  128);
    mmagemm<<<grdE,  blk>>>(m_feats, W_lg_nj,  nullptr, p_lg_nj, Ee,  128);
    mmagemm<<<grdE,  blk>>>(m_feats, W_g_fij,  nullptr, p_gfij,  Ee,  128);
    mmagemm<<<grdE2, blk>>>(x_feats, W_lg_fij, nullptr, p_lgfij, E2e, 128);
    mmagemm<<<grdN,  blk>>>(l_feats, W_g_ni,   nullptr, p_gni,   Nn,  128);
    mmagemm<<<grdN,  blk>>>(l_feats, W_g_nj,   nullptr, p_gnj,   Nn,  128);

    // ---- node-update inputs (CSR gather for agg) + GEMMs ----
    agg_m1_kernel<<<Ee, 128>>>(m_feats, x_feats);
    build_m2_kernel<<<(Ee * 256 + 255) / 256, 256>>>(l_feats, m_feats, gsrc, gdst);
    mmagemm<<<grdE, blk>>>(p_m1, W_lg_node, b_lg_node, p_h1, Ee, 256);
    mmagemm<<<grdE, blk>>>(p_m2, W_g_node,  b_g_node,  p_h2, Ee, 256);

    // ---- attention scores + softmax ----
    lg_score_kernel<<<(E2e * 32 + 255) / 256, 256>>>(lgsrc, lgdst, lg_attn, bias_lg);
    lgsoftmax_kernel<<<(Ee * 4 + 255) / 256, 256>>>();
    lgnorm_kernel<<<(E2e * 4 + 255) / 256, 256>>>(lgdst);
    g_score_kernel<<<(Ee * 32 + 255) / 256, 256>>>(gsrc, gdst, g_attn, bias_g);
    g_exp_kernel<<<(Ee * 4 + 255) / 256, 256>>>(gdst);
    ag_kernel   <<<(Ee * 4 + 255) / 256, 256>>>(gdst);

    // ---- fused gather + epilogue ----
    gather_final_kernel<<<Ee, 256>>>(lgsrc, (float*)d_out);
}